// round 3
// baseline (speedup 1.0000x reference)
#include <cuda_runtime.h>
#include <math.h>

// Problem constants
#define TT 2048
#define BBATCH 4
#define HH 16
#define EE 1024
#define FFDIM 4096
#define HDIM 64
#define NTOK (BBATCH*TT)        // 8192 tokens

// ---------------------------------------------------------------------------
// Scratch buffers (device globals; allocation is banned)
// ---------------------------------------------------------------------------
__device__ float g_q  [(size_t)NTOK * EE];
__device__ float g_k  [(size_t)NTOK * EE];
__device__ float g_v  [(size_t)NTOK * EE];
__device__ float g_ctx[(size_t)NTOK * EE];
__device__ float g_h  [(size_t)NTOK * EE];
__device__ float g_tmp[(size_t)NTOK * EE];
__device__ float g_ff [(size_t)NTOK * FFDIM];
__device__ float g_s  [(size_t)BBATCH * HH * TT * TT];   // 1 GiB scores/probs

// ---------------------------------------------------------------------------
// Generic SGEMM: C[M,N] = A[M,K] @ W[N,K]^T  (+bias, +relu per flags)
// 128x128 block, BK=16, 256 threads, 8x8 microtile per thread.
// flags: bit0 = add bias[col], bit1 = relu
// ---------------------------------------------------------------------------
__global__ __launch_bounds__(256) void sgemm_nt_kernel(
    const float* __restrict__ A, const float* __restrict__ W,
    const float* __restrict__ bias, float* __restrict__ C,
    int M, int N, int K, int flags)
{
    __shared__ float As[16][129];
    __shared__ float Bs[16][129];

    const int tid = threadIdx.x;
    const int tx = tid & 15;
    const int ty = tid >> 4;
    const int m0 = blockIdx.x * 128;
    const int n0 = blockIdx.y * 128;

    const float* Ab = A + (size_t)m0 * K;
    const float* Wb = W + (size_t)n0 * K;

    float acc[8][8];
#pragma unroll
    for (int i = 0; i < 8; i++)
#pragma unroll
        for (int j = 0; j < 8; j++) acc[i][j] = 0.f;

    const int lr = tid >> 2;         // 0..63
    const int lc = (tid & 3) * 4;    // 0,4,8,12

    for (int kt = 0; kt < K; kt += 16) {
#pragma unroll
        for (int hh = 0; hh < 2; hh++) {
            const int r = lr + hh * 64;
            float4 va = *(const float4*)(Ab + (size_t)r * K + kt + lc);
            As[lc + 0][r] = va.x; As[lc + 1][r] = va.y;
            As[lc + 2][r] = va.z; As[lc + 3][r] = va.w;
            float4 vb = *(const float4*)(Wb + (size_t)r * K + kt + lc);
            Bs[lc + 0][r] = vb.x; Bs[lc + 1][r] = vb.y;
            Bs[lc + 2][r] = vb.z; Bs[lc + 3][r] = vb.w;
        }
        __syncthreads();
#pragma unroll
        for (int k = 0; k < 16; k++) {
            float a[8], b[8];
#pragma unroll
            for (int i = 0; i < 4; i++) {
                a[i]     = As[k][ty * 4 + i];
                a[4 + i] = As[k][64 + ty * 4 + i];
            }
#pragma unroll
            for (int j = 0; j < 4; j++) {
                b[j]     = Bs[k][tx * 4 + j];
                b[4 + j] = Bs[k][64 + tx * 4 + j];
            }
#pragma unroll
            for (int i = 0; i < 8; i++)
#pragma unroll
                for (int j = 0; j < 8; j++)
                    acc[i][j] = fmaf(a[i], b[j], acc[i][j]);
        }
        __syncthreads();
    }

    // epilogue (vectorized float4 stores)
#pragma unroll
    for (int i = 0; i < 8; i++) {
        const int row = m0 + ((i < 4) ? (ty * 4 + i) : (64 + ty * 4 + (i - 4)));
#pragma unroll
        for (int jh = 0; jh < 2; jh++) {
            const int col = n0 + jh * 64 + tx * 4;
            float4 r4;
            r4.x = acc[i][jh * 4 + 0];
            r4.y = acc[i][jh * 4 + 1];
            r4.z = acc[i][jh * 4 + 2];
            r4.w = acc[i][jh * 4 + 3];
            if (flags & 1) {
                float4 b4 = *(const float4*)(bias + col);
                r4.x += b4.x; r4.y += b4.y; r4.z += b4.z; r4.w += b4.w;
            }
            if (flags & 2) {
                r4.x = fmaxf(r4.x, 0.f); r4.y = fmaxf(r4.y, 0.f);
                r4.z = fmaxf(r4.z, 0.f); r4.w = fmaxf(r4.w, 0.f);
            }
            *(float4*)(C + (size_t)row * N + col) = r4;
        }
    }
}

// ---------------------------------------------------------------------------
// Attention scores: S[z, q, k] = (Q . K) / 8, masked with key padding mask.
// Block computes a 128(q) x 128(k) tile for one (b,h). Reduction dim = 64.
// Dynamic smem: Qs[64][133] + Ks[64][133] (d-major transposed tiles).
// ---------------------------------------------------------------------------
#define SC_STRIDE 133
#define SC_SMEM (2 * 64 * SC_STRIDE * 4)

__global__ __launch_bounds__(256) void attn_scores_kernel(const int* __restrict__ mask)
{
    extern __shared__ float sm[];
    float (*Qs)[SC_STRIDE] = (float(*)[SC_STRIDE])sm;
    float (*Ks)[SC_STRIDE] = (float(*)[SC_STRIDE])(sm + 64 * SC_STRIDE);

    const int q0 = blockIdx.x * 128;
    const int k0 = blockIdx.y * 128;
    const int z  = blockIdx.z;           // b*H + h
    const int b  = z >> 4;
    const int h  = z & 15;
    const int tid = threadIdx.x;

    const float* qb = g_q + (size_t)b * TT * EE + h * HDIM;
    const float* kb = g_k + (size_t)b * TT * EE + h * HDIM;

#pragma unroll
    for (int it = 0; it < 32; it++) {
        const int idx = tid + it * 256;
        const int d = idx & 63;
        const int r = idx >> 6;
        Qs[d][r] = qb[(size_t)(q0 + r) * EE + d];
    }
#pragma unroll
    for (int it = 0; it < 32; it++) {
        const int idx = tid + it * 256;
        const int d = idx & 63;
        const int r = idx >> 6;
        Ks[d][r] = kb[(size_t)(k0 + r) * EE + d];
    }
    __syncthreads();

    const int tx = tid & 15;
    const int ty = tid >> 4;

    float acc[8][8];
#pragma unroll
    for (int i = 0; i < 8; i++)
#pragma unroll
        for (int j = 0; j < 8; j++) acc[i][j] = 0.f;

#pragma unroll 4
    for (int d = 0; d < 64; d++) {
        float a[8], bb[8];
#pragma unroll
        for (int i = 0; i < 4; i++) {
            a[i]     = Qs[d][ty * 4 + i];
            a[4 + i] = Qs[d][64 + ty * 4 + i];
        }
#pragma unroll
        for (int j = 0; j < 4; j++) {
            bb[j]     = Ks[d][tx * 4 + j];
            bb[4 + j] = Ks[d][64 + tx * 4 + j];
        }
#pragma unroll
        for (int i = 0; i < 8; i++)
#pragma unroll
            for (int j = 0; j < 8; j++)
                acc[i][j] = fmaf(a[i], bb[j], acc[i][j]);
    }

    const float NEG_INF = __int_as_float(0xff800000);
    // key-mask values for this thread's 8 columns (hoisted out of row loop)
    int mk[8];
#pragma unroll
    for (int jh = 0; jh < 2; jh++) {
        int4 m4 = *(const int4*)(mask + b * TT + k0 + jh * 64 + tx * 4);
        mk[jh * 4 + 0] = m4.x; mk[jh * 4 + 1] = m4.y;
        mk[jh * 4 + 2] = m4.z; mk[jh * 4 + 3] = m4.w;
    }

#pragma unroll
    for (int i = 0; i < 8; i++) {
        const int row = q0 + ((i < 4) ? (ty * 4 + i) : (64 + ty * 4 + (i - 4)));
        float* srow = g_s + ((size_t)z * TT + row) * TT;
#pragma unroll
        for (int jh = 0; jh < 2; jh++) {
            const int col = k0 + jh * 64 + tx * 4;
            float4 r4;
            r4.x = mk[jh * 4 + 0] ? acc[i][jh * 4 + 0] * 0.125f : NEG_INF;
            r4.y = mk[jh * 4 + 1] ? acc[i][jh * 4 + 1] * 0.125f : NEG_INF;
            r4.z = mk[jh * 4 + 2] ? acc[i][jh * 4 + 2] * 0.125f : NEG_INF;
            r4.w = mk[jh * 4 + 3] ? acc[i][jh * 4 + 3] * 0.125f : NEG_INF;
            *(float4*)(srow + col) = r4;
        }
    }
}

// ---------------------------------------------------------------------------
// Row softmax over K=2048 with query-mask scaling. One block per row.
// ---------------------------------------------------------------------------
__global__ __launch_bounds__(256) void softmax_kernel(const int* __restrict__ mask)
{
    __shared__ float sh[8];
    const size_t row = blockIdx.x;
    const int z = (int)(row >> 11);
    const int qpos = (int)(row & 2047);
    const int b = z >> 4;
    float* s = g_s + row * (size_t)TT;
    const int tid = threadIdx.x;

    float4 v0 = *(const float4*)(s + tid * 8);
    float4 v1 = *(const float4*)(s + tid * 8 + 4);
    float v[8] = {v0.x, v0.y, v0.z, v0.w, v1.x, v1.y, v1.z, v1.w};

    float m = v[0];
#pragma unroll
    for (int i = 1; i < 8; i++) m = fmaxf(m, v[i]);
#pragma unroll
    for (int o = 16; o > 0; o >>= 1) m = fmaxf(m, __shfl_xor_sync(0xffffffffu, m, o));
    if ((tid & 31) == 0) sh[tid >> 5] = m;
    __syncthreads();
    float mm = fmaxf(fmaxf(fmaxf(sh[0], sh[1]), fmaxf(sh[2], sh[3])),
                     fmaxf(fmaxf(sh[4], sh[5]), fmaxf(sh[6], sh[7])));
    if (mm < -1e37f) mm = 0.f;   // fully-masked row guard (never NaN)

    float sum = 0.f;
#pragma unroll
    for (int i = 0; i < 8; i++) { v[i] = expf(v[i] - mm); sum += v[i]; }
#pragma unroll
    for (int o = 16; o > 0; o >>= 1) sum += __shfl_xor_sync(0xffffffffu, sum, o);
    __syncthreads();
    if ((tid & 31) == 0) sh[tid >> 5] = sum;
    __syncthreads();
    float tot = sh[0] + sh[1] + sh[2] + sh[3] + sh[4] + sh[5] + sh[6] + sh[7];

    const float qm = (float)mask[b * TT + qpos];
    const float inv = (tot > 0.f) ? qm / tot : 0.f;

    float4 o0, o1;
    o0.x = v[0] * inv; o0.y = v[1] * inv; o0.z = v[2] * inv; o0.w = v[3] * inv;
    o1.x = v[4] * inv; o1.y = v[5] * inv; o1.z = v[6] * inv; o1.w = v[7] * inv;
    *(float4*)(s + tid * 8) = o0;
    *(float4*)(s + tid * 8 + 4) = o1;
}

// ---------------------------------------------------------------------------
// PV: ctx[b,q,h,d] = sum_k P[z,q,k] * V[b,k,h,d].
// Block computes 128(q) x 64(d) for one (b,h); loops K=2048 in 64-chunks.
// Dynamic smem: Ps[64][133] (k-major) + Vs[64][65].
// ---------------------------------------------------------------------------
#define PV_SMEM (64 * 133 * 4 + 64 * 65 * 4)

__global__ __launch_bounds__(256) void attn_pv_kernel()
{
    extern __shared__ float sm[];
    float (*Ps)[133] = (float(*)[133])sm;
    float (*Vs)[65]  = (float(*)[65])(sm + 64 * 133);

    const int q0 = blockIdx.x * 128;
    const int z  = blockIdx.y;
    const int b  = z >> 4;
    const int h  = z & 15;
    const int tid = threadIdx.x;
    const int tx = tid & 15;
    const int ty = tid >> 4;

    const float* vb = g_v + (size_t)b * TT * EE + h * HDIM;
    const float* pb = g_s + (size_t)z * TT * TT;

    float acc[8][4];
#pragma unroll
    for (int i = 0; i < 8; i++)
#pragma unroll
        for (int j = 0; j < 4; j++) acc[i][j] = 0.f;

    for (int kb = 0; kb < TT; kb += 64) {
#pragma unroll
        for (int it = 0; it < 32; it++) {
            const int idx = tid + it * 256;
            const int k = idx & 63;
            const int qi = idx >> 6;
            Ps[k][qi] = pb[(size_t)(q0 + qi) * TT + kb + k];
        }
#pragma unroll
        for (int it = 0; it < 16; it++) {
            const int idx = tid + it * 256;
            const int d = idx & 63;
            const int k = idx >> 6;
            Vs[k][d] = vb[(size_t)(kb + k) * EE + d];
        }
        __syncthreads();
#pragma unroll 4
        for (int k = 0; k < 64; k++) {
            float a[8], bb[4];
#pragma unroll
            for (int i = 0; i < 4; i++) {
                a[i]     = Ps[k][ty * 4 + i];
                a[4 + i] = Ps[k][64 + ty * 4 + i];
            }
#pragma unroll
            for (int j = 0; j < 4; j++) bb[j] = Vs[k][tx * 4 + j];
#pragma unroll
            for (int i = 0; i < 8; i++)
#pragma unroll
                for (int j = 0; j < 4; j++)
                    acc[i][j] = fmaf(a[i], bb[j], acc[i][j]);
        }
        __syncthreads();
    }

#pragma unroll
    for (int i = 0; i < 8; i++) {
        const int row = q0 + ((i < 4) ? (ty * 4 + i) : (64 + ty * 4 + (i - 4)));
        float4 r4;
        r4.x = acc[i][0]; r4.y = acc[i][1]; r4.z = acc[i][2]; r4.w = acc[i][3];
        *(float4*)(g_ctx + (size_t)(b * TT + row) * EE + h * HDIM + tx * 4) = r4;
    }
}

// ---------------------------------------------------------------------------
// out = LayerNorm(A + B) with ddof=1 std and (x-mean)/(sd+eps)*g + beta.
// One block per row of 1024; 4 elems/thread.
// ---------------------------------------------------------------------------
__global__ __launch_bounds__(256) void add_ln_kernel(
    const float* __restrict__ A, const float* __restrict__ Bv,
    const float* __restrict__ gam, const float* __restrict__ bet,
    float* __restrict__ out)
{
    __shared__ float shs[8], shq[8];
    const int row = blockIdx.x;
    const int tid = threadIdx.x;
    const size_t base = (size_t)row * EE + tid * 4;

    float4 a = *(const float4*)(A + base);
    float4 b = *(const float4*)(Bv + base);
    float x0 = a.x + b.x, x1 = a.y + b.y, x2 = a.z + b.z, x3 = a.w + b.w;

    float s = x0 + x1 + x2 + x3;
    float q = x0 * x0 + x1 * x1 + x2 * x2 + x3 * x3;
#pragma unroll
    for (int o = 16; o > 0; o >>= 1) {
        s += __shfl_xor_sync(0xffffffffu, s, o);
        q += __shfl_xor_sync(0xffffffffu, q, o);
    }
    if ((tid & 31) == 0) { shs[tid >> 5] = s; shq[tid >> 5] = q; }
    __syncthreads();
    float st = shs[0] + shs[1] + shs[2] + shs[3] + shs[4] + shs[5] + shs[6] + shs[7];
    float qt = shq[0] + shq[1] + shq[2] + shq[3] + shq[4] + shq[5] + shq[6] + shq[7];

    const float mean = st * (1.f / 1024.f);
    const float var = (qt - 1024.f * mean * mean) * (1.f / 1023.f);
    const float r = 1.f / (sqrtf(fmaxf(var, 0.f)) + 1e-5f);

    float4 g4 = *(const float4*)(gam + tid * 4);
    float4 b4 = *(const float4*)(bet + tid * 4);
    float4 o;
    o.x = (x0 - mean) * r * g4.x + b4.x;
    o.y = (x1 - mean) * r * g4.y + b4.y;
    o.z = (x2 - mean) * r * g4.z + b4.z;
    o.w = (x3 - mean) * r * g4.w + b4.w;
    *(float4*)(out + base) = o;
}

// ---------------------------------------------------------------------------
// Host launcher (graph-capturable: kernel launches only)
// ---------------------------------------------------------------------------
extern "C" void kernel_launch(void* const* d_in, const int* in_sizes, int n_in,
                              void* d_out, int out_size)
{
    const float* x    = (const float*)d_in[0];
    const int*   mask = (const int*)  d_in[1];
    const float* Wq   = (const float*)d_in[2];
    const float* Wk   = (const float*)d_in[3];
    const float* Wv   = (const float*)d_in[4];
    const float* Wo   = (const float*)d_in[5];
    const float* w1   = (const float*)d_in[6];
    const float* b1   = (const float*)d_in[7];
    const float* w2   = (const float*)d_in[8];
    const float* b2   = (const float*)d_in[9];
    const float* lng  = (const float*)d_in[10];
    const float* lnb  = (const float*)d_in[11];
    float* out = (float*)d_out;

    float *q, *k, *v, *ctx, *h, *tmp, *ff;
    cudaGetSymbolAddress((void**)&q,   g_q);
    cudaGetSymbolAddress((void**)&k,   g_k);
    cudaGetSymbolAddress((void**)&v,   g_v);
    cudaGetSymbolAddress((void**)&ctx, g_ctx);
    cudaGetSymbolAddress((void**)&h,   g_h);
    cudaGetSymbolAddress((void**)&tmp, g_tmp);
    cudaGetSymbolAddress((void**)&ff,  g_ff);

    cudaFuncSetAttribute(attn_scores_kernel,
                         cudaFuncAttributeMaxDynamicSharedMemorySize, SC_SMEM);
    cudaFuncSetAttribute(attn_pv_kernel,
                         cudaFuncAttributeMaxDynamicSharedMemorySize, PV_SMEM);

    const dim3 thr(256);

    // Projections
    sgemm_nt_kernel<<<dim3(64, 8),  thr>>>(x, Wq, nullptr, q, NTOK, EE, EE, 0);
    sgemm_nt_kernel<<<dim3(64, 8),  thr>>>(x, Wk, nullptr, k, NTOK, EE, EE, 0);
    sgemm_nt_kernel<<<dim3(64, 8),  thr>>>(x, Wv, nullptr, v, NTOK, EE, EE, 0);

    // Attention
    attn_scores_kernel<<<dim3(16, 16, 64), thr, SC_SMEM>>>(mask);
    softmax_kernel<<<BBATCH * HH * TT, thr>>>(mask);
    attn_pv_kernel<<<dim3(16, 64), thr, PV_SMEM>>>();

    // Output projection + first residual LN
    sgemm_nt_kernel<<<dim3(64, 8),  thr>>>(ctx, Wo, nullptr, tmp, NTOK, EE, EE, 0);
    add_ln_kernel<<<NTOK, thr>>>(tmp, x, lng, lnb, h);

    // FFN + second residual LN
    sgemm_nt_kernel<<<dim3(64, 32), thr>>>(h,  w1, b1, ff,  NTOK, FFDIM, EE, 3);
    sgemm_nt_kernel<<<dim3(64, 8),  thr>>>(ff, w2, b2, tmp, NTOK, EE, FFDIM, 1);
    add_ln_kernel<<<NTOK, thr>>>(tmp, h, lng, lnb, out);
}

// round 4
// speedup vs baseline: 1.6529x; 1.6529x over previous
#include <cuda_runtime.h>
#include <cuda_bf16.h>
#include <math.h>
#include <stdint.h>

// Problem constants
#define TT 2048
#define BBATCH 4
#define HH 16
#define EE 1024
#define FFDIM 4096
#define HDIM 64
#define NTOK (BBATCH*TT)        // 8192 tokens

// ---------------------------------------------------------------------------
// Scratch buffers (device globals; allocation is banned)
// ---------------------------------------------------------------------------
__device__ float g_q  [(size_t)NTOK * EE];
__device__ float g_k  [(size_t)NTOK * EE];
__device__ float g_v  [(size_t)NTOK * EE];
__device__ float g_ctx[(size_t)NTOK * EE];
__device__ float g_h  [(size_t)NTOK * EE];
__device__ float g_tmp[(size_t)NTOK * EE];
__device__ float g_ff [(size_t)NTOK * FFDIM];
__device__ float g_s  [(size_t)BBATCH * HH * TT * TT];   // 1 GiB scores/probs

// bf16 hi/lo interleaved ("X2") buffers: for n fp32 elems -> n uint32 words,
// laid out as [hi pair (2 bf16), lo pair (2 bf16)] per 2 consecutive elems.
__device__ uint32_t g_x2  [(size_t)NTOK * EE];
__device__ uint32_t g_ctx2[(size_t)NTOK * EE];
__device__ uint32_t g_h2  [(size_t)NTOK * EE];
__device__ uint32_t g_ff2 [(size_t)NTOK * FFDIM];
__device__ uint32_t g_wq2 [(size_t)EE * EE];
__device__ uint32_t g_wk2 [(size_t)EE * EE];
__device__ uint32_t g_wv2 [(size_t)EE * EE];
__device__ uint32_t g_wo2 [(size_t)EE * EE];
__device__ uint32_t g_w12 [(size_t)FFDIM * EE];
__device__ uint32_t g_w22 [(size_t)EE * FFDIM];

// ---------------------------------------------------------------------------
// fp32 -> interleaved bf16 hi/lo conversion. 4 elems (= 2 pairs) per thread.
// ---------------------------------------------------------------------------
__device__ __forceinline__ uint32_t bpack(__nv_bfloat16 a, __nv_bfloat16 b) {
    __nv_bfloat162 t;
    t.x = a; t.y = b;
    return *reinterpret_cast<uint32_t*>(&t);
}

__global__ __launch_bounds__(256) void cvt_kernel(
    const float4* __restrict__ src, uint4* __restrict__ dst, int n4)
{
    int i = blockIdx.x * 256 + threadIdx.x;
    if (i >= n4) return;
    float4 v = src[i];
    __nv_bfloat16 h0 = __float2bfloat16(v.x);
    __nv_bfloat16 h1 = __float2bfloat16(v.y);
    __nv_bfloat16 h2 = __float2bfloat16(v.z);
    __nv_bfloat16 h3 = __float2bfloat16(v.w);
    __nv_bfloat16 l0 = __float2bfloat16(v.x - __bfloat162float(h0));
    __nv_bfloat16 l1 = __float2bfloat16(v.y - __bfloat162float(h1));
    __nv_bfloat16 l2 = __float2bfloat16(v.z - __bfloat162float(h2));
    __nv_bfloat16 l3 = __float2bfloat16(v.w - __bfloat162float(h3));
    uint4 o;
    o.x = bpack(h0, h1);   // hi pair 0
    o.y = bpack(l0, l1);   // lo pair 0
    o.z = bpack(h2, h3);   // hi pair 1
    o.w = bpack(l2, l3);   // lo pair 1
    dst[i] = o;
}

// ---------------------------------------------------------------------------
// bf16x3 tensor-core GEMM: C[M,N] = A[M,K] @ W[N,K]^T (fp32-emulated via
// split bf16: hi*hi + hi*lo + lo*hi, fp32 accumulate).
// 128x128 block, BK=32, 256 threads (8 warps, 2x4; warp tile 64x32),
// mma.sync.m16n8k16.bf16, cp.async double-buffered smem.
// flags: bit0 = add bias[col], bit1 = relu
// smem row layout per tile: 128 rows x (32 u32 data + 8 u32 pad) = 160B rows.
// ---------------------------------------------------------------------------
#define GR_STRIDE 40                 // u32 per smem row
#define TILE_U32 (128 * GR_STRIDE)   // 5120 u32 = 20KB
#define BUF_U32  (2 * TILE_U32)      // A + B per buffer
#define GEMM_SMEM (2 * BUF_U32 * 4)  // 81920 B

__device__ __forceinline__ void cp_async16(uint32_t* smem_dst, const uint32_t* gsrc) {
    unsigned saddr = (unsigned)__cvta_generic_to_shared(smem_dst);
    asm volatile("cp.async.cg.shared.global [%0], [%1], 16;\n"
                 :: "r"(saddr), "l"(gsrc));
}

__device__ __forceinline__ void mma16816(float* c, const uint32_t* a, const uint32_t* b) {
    asm volatile(
        "mma.sync.aligned.m16n8k16.row.col.f32.bf16.bf16.f32 "
        "{%0,%1,%2,%3}, {%4,%5,%6,%7}, {%8,%9}, {%0,%1,%2,%3};"
        : "+f"(c[0]), "+f"(c[1]), "+f"(c[2]), "+f"(c[3])
        : "r"(a[0]), "r"(a[1]), "r"(a[2]), "r"(a[3]),
          "r"(b[0]), "r"(b[1]));
}

__global__ __launch_bounds__(256, 1) void gemm_bf16x3_kernel(
    const uint32_t* __restrict__ A2, const uint32_t* __restrict__ W2,
    const float* __restrict__ bias, float* __restrict__ C,
    int M, int N, int K, int flags)
{
    extern __shared__ uint32_t sm2[];

    const int tid  = threadIdx.x;
    const int warp = tid >> 5;
    const int lane = tid & 31;
    const int g = lane >> 2;
    const int t = lane & 3;
    const int wm = warp >> 2;      // 0..1
    const int wn = warp & 3;       // 0..3
    const int m0 = blockIdx.x * 128;
    const int n0 = blockIdx.y * 128;

    // X2 format: row of K elems = K uint32 words (hi/lo interleaved by pairs).
    const uint32_t* Ab = A2 + (size_t)m0 * K;
    const uint32_t* Wb = W2 + (size_t)n0 * K;

    float acc[4][4][4];
#pragma unroll
    for (int i = 0; i < 4; i++)
#pragma unroll
        for (int j = 0; j < 4; j++)
#pragma unroll
            for (int c = 0; c < 4; c++) acc[i][j][c] = 0.f;

    // ---- tile loader: 1024 chunks of 16B per tile (A and B) ----
    auto load_tiles = [&](int buf, int kt) {
        uint32_t* sA = sm2 + buf * BUF_U32;
        uint32_t* sB = sA + TILE_U32;
#pragma unroll
        for (int i = 0; i < 4; i++) {
            int c  = tid + i * 256;      // 0..1023
            int r  = c >> 3;             // row 0..127
            int cv = c & 7;              // 16B chunk 0..7
            cp_async16(sA + r * GR_STRIDE + cv * 4,
                       Ab + (size_t)r * K + kt + cv * 4);
            cp_async16(sB + r * GR_STRIDE + cv * 4,
                       Wb + (size_t)r * K + kt + cv * 4);
        }
    };

    load_tiles(0, 0);
    asm volatile("cp.async.commit_group;\n" ::: "memory");
    int cur = 0;

    for (int kt = 0; kt < K; kt += 32) {
        asm volatile("cp.async.wait_group 0;\n" ::: "memory");
        __syncthreads();
        if (kt + 32 < K) {
            load_tiles(cur ^ 1, kt + 32);
            asm volatile("cp.async.commit_group;\n" ::: "memory");
        }

        const uint32_t* sAw = sm2 + cur * BUF_U32 + (wm * 64) * GR_STRIDE;
        const uint32_t* sBw = sm2 + cur * BUF_U32 + TILE_U32 + (wn * 32) * GR_STRIDE;

#pragma unroll
        for (int ks = 0; ks < 2; ks++) {     // two k16 halves of BK=32
            uint32_t ah[4][4], al[4][4], bh[4][2], bl[4][2];
#pragma unroll
            for (int mt = 0; mt < 4; mt++) {
                const uint32_t* p = sAw + (mt * 16 + g) * GR_STRIDE + ks * 16 + 2 * t;
                uint2 x0 = *(const uint2*)(p);                    // a0 hi,lo
                uint2 x2 = *(const uint2*)(p + 8);                // a2
                uint2 x1 = *(const uint2*)(p + 8 * GR_STRIDE);    // a1
                uint2 x3 = *(const uint2*)(p + 8 * GR_STRIDE + 8);// a3
                ah[mt][0] = x0.x; al[mt][0] = x0.y;
                ah[mt][1] = x1.x; al[mt][1] = x1.y;
                ah[mt][2] = x2.x; al[mt][2] = x2.y;
                ah[mt][3] = x3.x; al[mt][3] = x3.y;
            }
#pragma unroll
            for (int nt = 0; nt < 4; nt++) {
                const uint32_t* p = sBw + (nt * 8 + g) * GR_STRIDE + ks * 16 + 2 * t;
                uint2 y0 = *(const uint2*)(p);       // b0 hi,lo
                uint2 y1 = *(const uint2*)(p + 8);   // b1
                bh[nt][0] = y0.x; bl[nt][0] = y0.y;
                bh[nt][1] = y1.x; bl[nt][1] = y1.y;
            }
#pragma unroll
            for (int mt = 0; mt < 4; mt++)
#pragma unroll
                for (int nt = 0; nt < 4; nt++) {
                    mma16816(acc[mt][nt], ah[mt], bh[nt]);  // hi*hi
                    mma16816(acc[mt][nt], ah[mt], bl[nt]);  // hi*lo
                    mma16816(acc[mt][nt], al[mt], bh[nt]);  // lo*hi
                }
        }
        cur ^= 1;
        __syncthreads();
    }

    // ---- epilogue ----
    // c0:(g,2t) c1:(g,2t+1) c2:(g+8,2t) c3:(g+8,2t+1)
#pragma unroll
    for (int mt = 0; mt < 4; mt++) {
        const int row0 = m0 + wm * 64 + mt * 16 + g;
#pragma unroll
        for (int nt = 0; nt < 4; nt++) {
            const int col = n0 + wn * 32 + nt * 8 + 2 * t;
            float2 v0 = make_float2(acc[mt][nt][0], acc[mt][nt][1]);
            float2 v1 = make_float2(acc[mt][nt][2], acc[mt][nt][3]);
            if (flags & 1) {
                float2 b2 = *(const float2*)(bias + col);
                v0.x += b2.x; v0.y += b2.y;
                v1.x += b2.x; v1.y += b2.y;
            }
            if (flags & 2) {
                v0.x = fmaxf(v0.x, 0.f); v0.y = fmaxf(v0.y, 0.f);
                v1.x = fmaxf(v1.x, 0.f); v1.y = fmaxf(v1.y, 0.f);
            }
            *(float2*)(C + (size_t)row0 * N + col) = v0;
            *(float2*)(C + (size_t)(row0 + 8) * N + col) = v1;
        }
    }
}

// ---------------------------------------------------------------------------
// Attention scores: S[z, q, k] = (Q . K) / 8, masked with key padding mask.
// ---------------------------------------------------------------------------
#define SC_STRIDE 133
#define SC_SMEM (2 * 64 * SC_STRIDE * 4)

__global__ __launch_bounds__(256) void attn_scores_kernel(const int* __restrict__ mask)
{
    extern __shared__ float sm[];
    float (*Qs)[SC_STRIDE] = (float(*)[SC_STRIDE])sm;
    float (*Ks)[SC_STRIDE] = (float(*)[SC_STRIDE])(sm + 64 * SC_STRIDE);

    const int q0 = blockIdx.x * 128;
    const int k0 = blockIdx.y * 128;
    const int z  = blockIdx.z;           // b*H + h
    const int b  = z >> 4;
    const int h  = z & 15;
    const int tid = threadIdx.x;

    const float* qb = g_q + (size_t)b * TT * EE + h * HDIM;
    const float* kb = g_k + (size_t)b * TT * EE + h * HDIM;

#pragma unroll
    for (int it = 0; it < 32; it++) {
        const int idx = tid + it * 256;
        const int d = idx & 63;
        const int r = idx >> 6;
        Qs[d][r] = qb[(size_t)(q0 + r) * EE + d];
    }
#pragma unroll
    for (int it = 0; it < 32; it++) {
        const int idx = tid + it * 256;
        const int d = idx & 63;
        const int r = idx >> 6;
        Ks[d][r] = kb[(size_t)(k0 + r) * EE + d];
    }
    __syncthreads();

    const int tx = tid & 15;
    const int ty = tid >> 4;

    float acc[8][8];
#pragma unroll
    for (int i = 0; i < 8; i++)
#pragma unroll
        for (int j = 0; j < 8; j++) acc[i][j] = 0.f;

#pragma unroll 4
    for (int d = 0; d < 64; d++) {
        float a[8], bb[8];
#pragma unroll
        for (int i = 0; i < 4; i++) {
            a[i]     = Qs[d][ty * 4 + i];
            a[4 + i] = Qs[d][64 + ty * 4 + i];
        }
#pragma unroll
        for (int j = 0; j < 4; j++) {
            bb[j]     = Ks[d][tx * 4 + j];
            bb[4 + j] = Ks[d][64 + tx * 4 + j];
        }
#pragma unroll
        for (int i = 0; i < 8; i++)
#pragma unroll
            for (int j = 0; j < 8; j++)
                acc[i][j] = fmaf(a[i], bb[j], acc[i][j]);
    }

    const float NEG_INF = __int_as_float(0xff800000);
    int mk[8];
#pragma unroll
    for (int jh = 0; jh < 2; jh++) {
        int4 m4 = *(const int4*)(mask + b * TT + k0 + jh * 64 + tx * 4);
        mk[jh * 4 + 0] = m4.x; mk[jh * 4 + 1] = m4.y;
        mk[jh * 4 + 2] = m4.z; mk[jh * 4 + 3] = m4.w;
    }

#pragma unroll
    for (int i = 0; i < 8; i++) {
        const int row = q0 + ((i < 4) ? (ty * 4 + i) : (64 + ty * 4 + (i - 4)));
        float* srow = g_s + ((size_t)z * TT + row) * TT;
#pragma unroll
        for (int jh = 0; jh < 2; jh++) {
            const int col = k0 + jh * 64 + tx * 4;
            float4 r4;
            r4.x = mk[jh * 4 + 0] ? acc[i][jh * 4 + 0] * 0.125f : NEG_INF;
            r4.y = mk[jh * 4 + 1] ? acc[i][jh * 4 + 1] * 0.125f : NEG_INF;
            r4.z = mk[jh * 4 + 2] ? acc[i][jh * 4 + 2] * 0.125f : NEG_INF;
            r4.w = mk[jh * 4 + 3] ? acc[i][jh * 4 + 3] * 0.125f : NEG_INF;
            *(float4*)(srow + col) = r4;
        }
    }
}

// ---------------------------------------------------------------------------
// Row softmax over K=2048 with query-mask scaling. One block per row.
// ---------------------------------------------------------------------------
__global__ __launch_bounds__(256) void softmax_kernel(const int* __restrict__ mask)
{
    __shared__ float sh[8];
    const size_t row = blockIdx.x;
    const int z = (int)(row >> 11);
    const int qpos = (int)(row & 2047);
    const int b = z >> 4;
    float* s = g_s + row * (size_t)TT;
    const int tid = threadIdx.x;

    float4 v0 = *(const float4*)(s + tid * 8);
    float4 v1 = *(const float4*)(s + tid * 8 + 4);
    float v[8] = {v0.x, v0.y, v0.z, v0.w, v1.x, v1.y, v1.z, v1.w};

    float m = v[0];
#pragma unroll
    for (int i = 1; i < 8; i++) m = fmaxf(m, v[i]);
#pragma unroll
    for (int o = 16; o > 0; o >>= 1) m = fmaxf(m, __shfl_xor_sync(0xffffffffu, m, o));
    if ((tid & 31) == 0) sh[tid >> 5] = m;
    __syncthreads();
    float mm = fmaxf(fmaxf(fmaxf(sh[0], sh[1]), fmaxf(sh[2], sh[3])),
                     fmaxf(fmaxf(sh[4], sh[5]), fmaxf(sh[6], sh[7])));
    if (mm < -1e37f) mm = 0.f;

    float sum = 0.f;
#pragma unroll
    for (int i = 0; i < 8; i++) { v[i] = expf(v[i] - mm); sum += v[i]; }
#pragma unroll
    for (int o = 16; o > 0; o >>= 1) sum += __shfl_xor_sync(0xffffffffu, sum, o);
    __syncthreads();
    if ((tid & 31) == 0) sh[tid >> 5] = sum;
    __syncthreads();
    float tot = sh[0] + sh[1] + sh[2] + sh[3] + sh[4] + sh[5] + sh[6] + sh[7];

    const float qm = (float)mask[b * TT + qpos];
    const float inv = (tot > 0.f) ? qm / tot : 0.f;

    float4 o0, o1;
    o0.x = v[0] * inv; o0.y = v[1] * inv; o0.z = v[2] * inv; o0.w = v[3] * inv;
    o1.x = v[4] * inv; o1.y = v[5] * inv; o1.z = v[6] * inv; o1.w = v[7] * inv;
    *(float4*)(s + tid * 8) = o0;
    *(float4*)(s + tid * 8 + 4) = o1;
}

// ---------------------------------------------------------------------------
// PV: ctx[b,q,h,d] = sum_k P[z,q,k] * V[b,k,h,d].
// ---------------------------------------------------------------------------
#define PV_SMEM (64 * 133 * 4 + 64 * 65 * 4)

__global__ __launch_bounds__(256) void attn_pv_kernel()
{
    extern __shared__ float sm[];
    float (*Ps)[133] = (float(*)[133])sm;
    float (*Vs)[65]  = (float(*)[65])(sm + 64 * 133);

    const int q0 = blockIdx.x * 128;
    const int z  = blockIdx.y;
    const int b  = z >> 4;
    const int h  = z & 15;
    const int tid = threadIdx.x;
    const int tx = tid & 15;
    const int ty = tid >> 4;

    const float* vb = g_v + (size_t)b * TT * EE + h * HDIM;
    const float* pb = g_s + (size_t)z * TT * TT;

    float acc[8][4];
#pragma unroll
    for (int i = 0; i < 8; i++)
#pragma unroll
        for (int j = 0; j < 4; j++) acc[i][j] = 0.f;

    for (int kb = 0; kb < TT; kb += 64) {
#pragma unroll
        for (int it = 0; it < 32; it++) {
            const int idx = tid + it * 256;
            const int k = idx & 63;
            const int qi = idx >> 6;
            Ps[k][qi] = pb[(size_t)(q0 + qi) * TT + kb + k];
        }
#pragma unroll
        for (int it = 0; it < 16; it++) {
            const int idx = tid + it * 256;
            const int d = idx & 63;
            const int k = idx >> 6;
            Vs[k][d] = vb[(size_t)(kb + k) * EE + d];
        }
        __syncthreads();
#pragma unroll 4
        for (int k = 0; k < 64; k++) {
            float a[8], bb[4];
#pragma unroll
            for (int i = 0; i < 4; i++) {
                a[i]     = Ps[k][ty * 4 + i];
                a[4 + i] = Ps[k][64 + ty * 4 + i];
            }
#pragma unroll
            for (int j = 0; j < 4; j++) bb[j] = Vs[k][tx * 4 + j];
#pragma unroll
            for (int i = 0; i < 8; i++)
#pragma unroll
                for (int j = 0; j < 4; j++)
                    acc[i][j] = fmaf(a[i], bb[j], acc[i][j]);
        }
        __syncthreads();
    }

#pragma unroll
    for (int i = 0; i < 8; i++) {
        const int row = q0 + ((i < 4) ? (ty * 4 + i) : (64 + ty * 4 + (i - 4)));
        float4 r4;
        r4.x = acc[i][0]; r4.y = acc[i][1]; r4.z = acc[i][2]; r4.w = acc[i][3];
        *(float4*)(g_ctx + (size_t)(b * TT + row) * EE + h * HDIM + tx * 4) = r4;
    }
}

// ---------------------------------------------------------------------------
// out = LayerNorm(A + B) with ddof=1 std.
// ---------------------------------------------------------------------------
__global__ __launch_bounds__(256) void add_ln_kernel(
    const float* __restrict__ A, const float* __restrict__ Bv,
    const float* __restrict__ gam, const float* __restrict__ bet,
    float* __restrict__ out)
{
    __shared__ float shs[8], shq[8];
    const int row = blockIdx.x;
    const int tid = threadIdx.x;
    const size_t base = (size_t)row * EE + tid * 4;

    float4 a = *(const float4*)(A + base);
    float4 b = *(const float4*)(Bv + base);
    float x0 = a.x + b.x, x1 = a.y + b.y, x2 = a.z + b.z, x3 = a.w + b.w;

    float s = x0 + x1 + x2 + x3;
    float q = x0 * x0 + x1 * x1 + x2 * x2 + x3 * x3;
#pragma unroll
    for (int o = 16; o > 0; o >>= 1) {
        s += __shfl_xor_sync(0xffffffffu, s, o);
        q += __shfl_xor_sync(0xffffffffu, q, o);
    }
    if ((tid & 31) == 0) { shs[tid >> 5] = s; shq[tid >> 5] = q; }
    __syncthreads();
    float st = shs[0] + shs[1] + shs[2] + shs[3] + shs[4] + shs[5] + shs[6] + shs[7];
    float qt = shq[0] + shq[1] + shq[2] + shq[3] + shq[4] + shq[5] + shq[6] + shq[7];

    const float mean = st * (1.f / 1024.f);
    const float var = (qt - 1024.f * mean * mean) * (1.f / 1023.f);
    const float r = 1.f / (sqrtf(fmaxf(var, 0.f)) + 1e-5f);

    float4 g4 = *(const float4*)(gam + tid * 4);
    float4 b4 = *(const float4*)(bet + tid * 4);
    float4 o;
    o.x = (x0 - mean) * r * g4.x + b4.x;
    o.y = (x1 - mean) * r * g4.y + b4.y;
    o.z = (x2 - mean) * r * g4.z + b4.z;
    o.w = (x3 - mean) * r * g4.w + b4.w;
    *(float4*)(out + base) = o;
}

// ---------------------------------------------------------------------------
// Host launcher (graph-capturable: kernel launches only)
// ---------------------------------------------------------------------------
static inline void cvt(const float* src, uint32_t* dst, size_t n) {
    int n4 = (int)(n / 4);
    cvt_kernel<<<(n4 + 255) / 256, 256>>>((const float4*)src, (uint4*)dst, n4);
}

extern "C" void kernel_launch(void* const* d_in, const int* in_sizes, int n_in,
                              void* d_out, int out_size)
{
    const float* x    = (const float*)d_in[0];
    const int*   mask = (const int*)  d_in[1];
    const float* Wq   = (const float*)d_in[2];
    const float* Wk   = (const float*)d_in[3];
    const float* Wv   = (const float*)d_in[4];
    const float* Wo   = (const float*)d_in[5];
    const float* w1   = (const float*)d_in[6];
    const float* b1   = (const float*)d_in[7];
    const float* w2   = (const float*)d_in[8];
    const float* b2   = (const float*)d_in[9];
    const float* lng  = (const float*)d_in[10];
    const float* lnb  = (const float*)d_in[11];
    float* out = (float*)d_out;

    float *q, *k, *v, *ctx, *h, *tmp, *ff;
    cudaGetSymbolAddress((void**)&q,   g_q);
    cudaGetSymbolAddress((void**)&k,   g_k);
    cudaGetSymbolAddress((void**)&v,   g_v);
    cudaGetSymbolAddress((void**)&ctx, g_ctx);
    cudaGetSymbolAddress((void**)&h,   g_h);
    cudaGetSymbolAddress((void**)&tmp, g_tmp);
    cudaGetSymbolAddress((void**)&ff,  g_ff);

    uint32_t *x2, *ctx2, *h2, *ff2, *wq2, *wk2, *wv2, *wo2, *w12, *w22;
    cudaGetSymbolAddress((void**)&x2,   g_x2);
    cudaGetSymbolAddress((void**)&ctx2, g_ctx2);
    cudaGetSymbolAddress((void**)&h2,   g_h2);
    cudaGetSymbolAddress((void**)&ff2,  g_ff2);
    cudaGetSymbolAddress((void**)&wq2,  g_wq2);
    cudaGetSymbolAddress((void**)&wk2,  g_wk2);
    cudaGetSymbolAddress((void**)&wv2,  g_wv2);
    cudaGetSymbolAddress((void**)&wo2,  g_wo2);
    cudaGetSymbolAddress((void**)&w12,  g_w12);
    cudaGetSymbolAddress((void**)&w22,  g_w22);

    cudaFuncSetAttribute(gemm_bf16x3_kernel,
                         cudaFuncAttributeMaxDynamicSharedMemorySize, GEMM_SMEM);
    cudaFuncSetAttribute(attn_scores_kernel,
                         cudaFuncAttributeMaxDynamicSharedMemorySize, SC_SMEM);
    cudaFuncSetAttribute(attn_pv_kernel,
                         cudaFuncAttributeMaxDynamicSharedMemorySize, PV_SMEM);

    const dim3 thr(256);

    // Convert inputs + weights to interleaved bf16 hi/lo
    cvt(x,  x2,  (size_t)NTOK * EE);
    cvt(Wq, wq2, (size_t)EE * EE);
    cvt(Wk, wk2, (size_t)EE * EE);
    cvt(Wv, wv2, (size_t)EE * EE);
    cvt(Wo, wo2, (size_t)EE * EE);
    cvt(w1, w12, (size_t)FFDIM * EE);
    cvt(w2, w22, (size_t)EE * FFDIM);

    // QKV projections (tensor cores, bf16x3)
    gemm_bf16x3_kernel<<<dim3(64, 8), thr, GEMM_SMEM>>>(x2, wq2, nullptr, q, NTOK, EE, EE, 0);
    gemm_bf16x3_kernel<<<dim3(64, 8), thr, GEMM_SMEM>>>(x2, wk2, nullptr, k, NTOK, EE, EE, 0);
    gemm_bf16x3_kernel<<<dim3(64, 8), thr, GEMM_SMEM>>>(x2, wv2, nullptr, v, NTOK, EE, EE, 0);

    // Attention (fp32)
    attn_scores_kernel<<<dim3(16, 16, 64), thr, SC_SMEM>>>(mask);
    softmax_kernel<<<BBATCH * HH * TT, thr>>>(mask);
    attn_pv_kernel<<<dim3(16, 64), thr, PV_SMEM>>>();

    // Output projection + first residual LN
    cvt(ctx, ctx2, (size_t)NTOK * EE);
    gemm_bf16x3_kernel<<<dim3(64, 8), thr, GEMM_SMEM>>>(ctx2, wo2, nullptr, tmp, NTOK, EE, EE, 0);
    add_ln_kernel<<<NTOK, thr>>>(tmp, x, lng, lnb, h);

    // FFN + second residual LN
    cvt(h, h2, (size_t)NTOK * EE);
    gemm_bf16x3_kernel<<<dim3(64, 32), thr, GEMM_SMEM>>>(h2, w12, b1, ff, NTOK, FFDIM, EE, 3);
    cvt(ff, ff2, (size_t)NTOK * FFDIM);
    gemm_bf16x3_kernel<<<dim3(64, 8), thr, GEMM_SMEM>>>(ff2, w22, b2, tmp, NTOK, EE, FFDIM, 1);
    add_ln_kernel<<<NTOK, thr>>>(tmp, h, lng, lnb, out);
}

// round 5
// speedup vs baseline: 2.3291x; 1.4091x over previous
#include <cuda_runtime.h>
#include <cuda_bf16.h>
#include <math.h>
#include <stdint.h>

// Problem constants
#define TT 2048
#define BBATCH 4
#define HH 16
#define EE 1024
#define FFDIM 4096
#define HDIM 64
#define NTOK (BBATCH*TT)        // 8192 tokens

// ---------------------------------------------------------------------------
// Scratch buffers (device globals; allocation is banned)
// ---------------------------------------------------------------------------
__device__ float g_q  [(size_t)NTOK * EE];
__device__ float g_k  [(size_t)NTOK * EE];
__device__ float g_v  [(size_t)NTOK * EE];
__device__ float g_ctx[(size_t)NTOK * EE];
__device__ float g_h  [(size_t)NTOK * EE];
__device__ float g_tmp[(size_t)NTOK * EE];
__device__ float g_ff [(size_t)NTOK * FFDIM];

// bf16 hi/lo interleaved ("X2") buffers (1 u32 word per fp32 element):
// pair (2i,2i+1) -> word 2i = (bf16hi(e0),bf16hi(e1)), word 2i+1 = lo pair.
__device__ uint32_t g_x2  [(size_t)NTOK * EE];
__device__ uint32_t g_ctx2[(size_t)NTOK * EE];
__device__ uint32_t g_h2  [(size_t)NTOK * EE];
__device__ uint32_t g_ff2 [(size_t)NTOK * FFDIM];
__device__ uint32_t g_wq2 [(size_t)EE * EE];
__device__ uint32_t g_wk2 [(size_t)EE * EE];
__device__ uint32_t g_wv2 [(size_t)EE * EE];
__device__ uint32_t g_wo2 [(size_t)EE * EE];
__device__ uint32_t g_w12 [(size_t)FFDIM * EE];
__device__ uint32_t g_w22 [(size_t)EE * FFDIM];

// Per-head attention operands (X2 format):
// g_q2/g_k2: [z=b*H+h][t][d-words(64)]   g_vt2: [z][d][t-words(2048)]
__device__ uint32_t g_q2 [(size_t)64 * TT * HDIM];
__device__ uint32_t g_k2 [(size_t)64 * TT * HDIM];
__device__ uint32_t g_vt2[(size_t)64 * HDIM * TT];

// ---------------------------------------------------------------------------
// Small helpers
// ---------------------------------------------------------------------------
__device__ __forceinline__ uint32_t bpack(__nv_bfloat16 a, __nv_bfloat16 b) {
    __nv_bfloat162 t;
    t.x = a; t.y = b;
    return *reinterpret_cast<uint32_t*>(&t);
}

// pack (e0 -> low half, e1 -> high half); also produce residual (lo) word.
__device__ __forceinline__ uint32_t pack_hi_lo(float e0, float e1, uint32_t& lo) {
    uint32_t hi;
    asm("cvt.rn.bf16x2.f32 %0, %1, %2;" : "=r"(hi) : "f"(e1), "f"(e0));
    float r0 = e0 - __uint_as_float(hi << 16);
    float r1 = e1 - __uint_as_float(hi & 0xffff0000u);
    asm("cvt.rn.bf16x2.f32 %0, %1, %2;" : "=r"(lo) : "f"(r1), "f"(r0));
    return hi;
}

__device__ __forceinline__ float ex2(float x) {
    float r;
    asm("ex2.approx.f32 %0, %1;" : "=f"(r) : "f"(x));
    return r;
}

__device__ __forceinline__ void cp_async16(uint32_t* smem_dst, const uint32_t* gsrc) {
    unsigned saddr = (unsigned)__cvta_generic_to_shared(smem_dst);
    asm volatile("cp.async.cg.shared.global [%0], [%1], 16;\n"
                 :: "r"(saddr), "l"(gsrc));
}

__device__ __forceinline__ void mma16816(float* c, const uint32_t* a, const uint32_t* b) {
    asm volatile(
        "mma.sync.aligned.m16n8k16.row.col.f32.bf16.bf16.f32 "
        "{%0,%1,%2,%3}, {%4,%5,%6,%7}, {%8,%9}, {%0,%1,%2,%3};"
        : "+f"(c[0]), "+f"(c[1]), "+f"(c[2]), "+f"(c[3])
        : "r"(a[0]), "r"(a[1]), "r"(a[2]), "r"(a[3]),
          "r"(b[0]), "r"(b[1]));
}

// ---------------------------------------------------------------------------
// fp32 -> interleaved bf16 hi/lo conversion (linear layout).
// ---------------------------------------------------------------------------
__global__ __launch_bounds__(256) void cvt_kernel(
    const float4* __restrict__ src, uint4* __restrict__ dst, int n4)
{
    int i = blockIdx.x * 256 + threadIdx.x;
    if (i >= n4) return;
    float4 v = src[i];
    __nv_bfloat16 h0 = __float2bfloat16(v.x);
    __nv_bfloat16 h1 = __float2bfloat16(v.y);
    __nv_bfloat16 h2 = __float2bfloat16(v.z);
    __nv_bfloat16 h3 = __float2bfloat16(v.w);
    __nv_bfloat16 l0 = __float2bfloat16(v.x - __bfloat162float(h0));
    __nv_bfloat16 l1 = __float2bfloat16(v.y - __bfloat162float(h1));
    __nv_bfloat16 l2 = __float2bfloat16(v.z - __bfloat162float(h2));
    __nv_bfloat16 l3 = __float2bfloat16(v.w - __bfloat162float(h3));
    uint4 o;
    o.x = bpack(h0, h1);
    o.y = bpack(l0, l1);
    o.z = bpack(h2, h3);
    o.w = bpack(l2, l3);
    dst[i] = o;
}

// ---------------------------------------------------------------------------
// Repack fp32 [tok][E] (head-interleaved) -> per-head X2 [z][t][64 words].
// One thread per element pair; coalesced read & write.
// ---------------------------------------------------------------------------
__global__ __launch_bounds__(256) void repack_qk_kernel(
    const float* __restrict__ src, uint32_t* __restrict__ dst)
{
    size_t i = (size_t)blockIdx.x * 256 + threadIdx.x;  // pair index
    int pd = (int)(i & 31);
    size_t r = i >> 5;                 // z*TT + t
    int t = (int)(r & 2047);
    int z = (int)(r >> 11);
    int b = z >> 4, h = z & 15;
    float2 v = *(const float2*)(src + ((size_t)(b * TT + t)) * EE + h * 64 + pd * 2);
    __nv_bfloat16 h0 = __float2bfloat16(v.x);
    __nv_bfloat16 h1 = __float2bfloat16(v.y);
    __nv_bfloat16 l0 = __float2bfloat16(v.x - __bfloat162float(h0));
    __nv_bfloat16 l1 = __float2bfloat16(v.y - __bfloat162float(h1));
    uint2 o;
    o.x = bpack(h0, h1);
    o.y = bpack(l0, l1);
    *(uint2*)(dst + r * 64 + 2 * pd) = o;
}

// ---------------------------------------------------------------------------
// Repack V fp32 -> transposed per-head X2 g_vt2[z][d][t-words] via smem tiles.
// Block handles one 32(keys) x 32(d) tile for one z.
// ---------------------------------------------------------------------------
__global__ __launch_bounds__(256) void repack_vt_kernel(const float* __restrict__ src)
{
    __shared__ float tile[32][33];
    const int z = blockIdx.z, b = z >> 4, h = z & 15;
    const int d0 = blockIdx.y * 32;
    const int t0 = blockIdx.x * 32;
    const int tid = threadIdx.x;

#pragma unroll
    for (int i = 0; i < 4; i++) {
        int e = tid + i * 256;
        int kr = e >> 5, dc = e & 31;
        tile[kr][dc] = src[(size_t)(b * TT + t0 + kr) * EE + h * 64 + d0 + dc];
    }
    __syncthreads();
#pragma unroll
    for (int i = 0; i < 4; i++) {
        int e = tid + i * 256;
        int dr = e >> 5, kc = e & 31;
        int k0 = kc & ~1;
        float p0 = tile[k0][dr], p1 = tile[k0 + 1][dr];
        uint32_t lo, hi = pack_hi_lo(p0, p1, lo);
        g_vt2[((size_t)z * 64 + d0 + dr) * TT + t0 + kc] = (kc & 1) ? lo : hi;
    }
}

// ---------------------------------------------------------------------------
// bf16x3 tensor-core GEMM: C[M,N] = A[M,K] @ W[N,K]^T
// ---------------------------------------------------------------------------
#define GR_STRIDE 40
#define TILE_U32 (128 * GR_STRIDE)
#define BUF_U32  (2 * TILE_U32)
#define GEMM_SMEM (2 * BUF_U32 * 4)

__global__ __launch_bounds__(256, 1) void gemm_bf16x3_kernel(
    const uint32_t* __restrict__ A2, const uint32_t* __restrict__ W2,
    const float* __restrict__ bias, float* __restrict__ C,
    int M, int N, int K, int flags)
{
    extern __shared__ uint32_t sm2[];

    const int tid  = threadIdx.x;
    const int warp = tid >> 5;
    const int lane = tid & 31;
    const int g = lane >> 2;
    const int t = lane & 3;
    const int wm = warp >> 2;
    const int wn = warp & 3;
    const int m0 = blockIdx.x * 128;
    const int n0 = blockIdx.y * 128;

    const uint32_t* Ab = A2 + (size_t)m0 * K;
    const uint32_t* Wb = W2 + (size_t)n0 * K;

    float acc[4][4][4];
#pragma unroll
    for (int i = 0; i < 4; i++)
#pragma unroll
        for (int j = 0; j < 4; j++)
#pragma unroll
            for (int c = 0; c < 4; c++) acc[i][j][c] = 0.f;

    auto load_tiles = [&](int buf, int kt) {
        uint32_t* sA = sm2 + buf * BUF_U32;
        uint32_t* sB = sA + TILE_U32;
#pragma unroll
        for (int i = 0; i < 4; i++) {
            int c  = tid + i * 256;
            int r  = c >> 3;
            int cv = c & 7;
            cp_async16(sA + r * GR_STRIDE + cv * 4,
                       Ab + (size_t)r * K + kt + cv * 4);
            cp_async16(sB + r * GR_STRIDE + cv * 4,
                       Wb + (size_t)r * K + kt + cv * 4);
        }
    };

    load_tiles(0, 0);
    asm volatile("cp.async.commit_group;\n" ::: "memory");
    int cur = 0;

    for (int kt = 0; kt < K; kt += 32) {
        asm volatile("cp.async.wait_group 0;\n" ::: "memory");
        __syncthreads();
        if (kt + 32 < K) {
            load_tiles(cur ^ 1, kt + 32);
            asm volatile("cp.async.commit_group;\n" ::: "memory");
        }

        const uint32_t* sAw = sm2 + cur * BUF_U32 + (wm * 64) * GR_STRIDE;
        const uint32_t* sBw = sm2 + cur * BUF_U32 + TILE_U32 + (wn * 32) * GR_STRIDE;

#pragma unroll
        for (int ks = 0; ks < 2; ks++) {
            uint32_t ah[4][4], al[4][4], bh[4][2], bl[4][2];
#pragma unroll
            for (int mt = 0; mt < 4; mt++) {
                const uint32_t* p = sAw + (mt * 16 + g) * GR_STRIDE + ks * 16 + 2 * t;
                uint2 x0 = *(const uint2*)(p);
                uint2 x2 = *(const uint2*)(p + 8);
                uint2 x1 = *(const uint2*)(p + 8 * GR_STRIDE);
                uint2 x3 = *(const uint2*)(p + 8 * GR_STRIDE + 8);
                ah[mt][0] = x0.x; al[mt][0] = x0.y;
                ah[mt][1] = x1.x; al[mt][1] = x1.y;
                ah[mt][2] = x2.x; al[mt][2] = x2.y;
                ah[mt][3] = x3.x; al[mt][3] = x3.y;
            }
#pragma unroll
            for (int nt = 0; nt < 4; nt++) {
                const uint32_t* p = sBw + (nt * 8 + g) * GR_STRIDE + ks * 16 + 2 * t;
                uint2 y0 = *(const uint2*)(p);
                uint2 y1 = *(const uint2*)(p + 8);
                bh[nt][0] = y0.x; bl[nt][0] = y0.y;
                bh[nt][1] = y1.x; bl[nt][1] = y1.y;
            }
#pragma unroll
            for (int mt = 0; mt < 4; mt++)
#pragma unroll
                for (int nt = 0; nt < 4; nt++) {
                    mma16816(acc[mt][nt], ah[mt], bh[nt]);
                    mma16816(acc[mt][nt], ah[mt], bl[nt]);
                    mma16816(acc[mt][nt], al[mt], bh[nt]);
                }
        }
        cur ^= 1;
        __syncthreads();
    }

#pragma unroll
    for (int mt = 0; mt < 4; mt++) {
        const int row0 = m0 + wm * 64 + mt * 16 + g;
#pragma unroll
        for (int nt = 0; nt < 4; nt++) {
            const int col = n0 + wn * 32 + nt * 8 + 2 * t;
            float2 v0 = make_float2(acc[mt][nt][0], acc[mt][nt][1]);
            float2 v1 = make_float2(acc[mt][nt][2], acc[mt][nt][3]);
            if (flags & 1) {
                float2 b2 = *(const float2*)(bias + col);
                v0.x += b2.x; v0.y += b2.y;
                v1.x += b2.x; v1.y += b2.y;
            }
            if (flags & 2) {
                v0.x = fmaxf(v0.x, 0.f); v0.y = fmaxf(v0.y, 0.f);
                v1.x = fmaxf(v1.x, 0.f); v1.y = fmaxf(v1.y, 0.f);
            }
            *(float2*)(C + (size_t)row0 * N + col) = v0;
            *(float2*)(C + (size_t)(row0 + 8) * N + col) = v1;
        }
    }
}

// ---------------------------------------------------------------------------
// Fused flash attention, bf16x3 MMA, online softmax.
// Block: 256 threads (8 warps), one (z = b*H+h, 128-row q-tile).
// Warp w owns q rows [w*16, w*16+16). K-loop in 64-key tiles, double-buffered.
// ---------------------------------------------------------------------------
#define AT_STRIDE 68                       // u32 words per padded smem row
#define AT_UQ     0                        // Q: 128 x 68
#define AT_KT     (128 * AT_STRIDE)        // K tiles: 2 x 64 x 68
#define AT_VT     (AT_KT + 2 * 64 * AT_STRIDE)
#define AT_BIAS   (AT_VT + 2 * 64 * AT_STRIDE)  // float[2][64]
#define AT_SMEM   ((AT_BIAS + 128) * 4)

__global__ __launch_bounds__(256, 1) void attn_fused_kernel(const int* __restrict__ mask)
{
    extern __shared__ uint32_t sm[];
    uint32_t* uq = sm + AT_UQ;
    float* biasbuf = (float*)(sm + AT_BIAS);

    const int tid  = threadIdx.x;
    const int warp = tid >> 5;
    const int lane = tid & 31;
    const int g = lane >> 2;
    const int t = lane & 3;

    const int q0 = blockIdx.x * 128;
    const int z  = blockIdx.y;
    const int b  = z >> 4;

    const uint32_t* qg = g_q2 + ((size_t)z * TT + q0) * 64;
    const uint32_t* kg = g_k2 + (size_t)z * TT * 64;
    const uint32_t* vg = g_vt2 + (size_t)z * 64 * TT;

    // stage Q (128 rows x 64 words): 2048 x 16B chunks
#pragma unroll
    for (int i = 0; i < 8; i++) {
        int c = tid + i * 256;
        int r = c >> 4, cv = c & 15;
        cp_async16(uq + r * AT_STRIDE + cv * 4, qg + (size_t)r * 64 + cv * 4);
    }

    auto load_kv = [&](int buf, int kb) {
        uint32_t* sk = sm + AT_KT + buf * 64 * AT_STRIDE;
        uint32_t* sv = sm + AT_VT + buf * 64 * AT_STRIDE;
#pragma unroll
        for (int i = 0; i < 4; i++) {
            int c = tid + i * 256;
            int r = c >> 4, cv = c & 15;
            cp_async16(sk + r * AT_STRIDE + cv * 4,
                       kg + (size_t)(kb + r) * 64 + cv * 4);
            cp_async16(sv + r * AT_STRIDE + cv * 4,
                       vg + (size_t)r * TT + kb + cv * 4);
        }
        if (tid < 64)
            biasbuf[buf * 64 + tid] = mask[b * TT + kb + tid] ? 0.f : -1e30f;
    };

    load_kv(0, 0);
    asm volatile("cp.async.commit_group;\n" ::: "memory");

    float o[8][4];
#pragma unroll
    for (int dn = 0; dn < 8; dn++)
#pragma unroll
        for (int c = 0; c < 4; c++) o[dn][c] = 0.f;

    float m0 = -1e4f, m1 = -1e4f, l0 = 0.f, l1 = 0.f;
    uint32_t qh[4][4], ql[4][4];
    const float SC = 0.125f * 1.44269504088896340736f;  // 1/8 * log2(e)

    int cur = 0;
    for (int kb = 0; kb < TT; kb += 64) {
        asm volatile("cp.async.wait_group 0;\n" ::: "memory");
        __syncthreads();

        if (kb == 0) {
            // load Q fragments once (rows w*16+g / +8; k = kf*16 + 2t (+8))
            const uint32_t* qw = uq + (warp * 16 + g) * AT_STRIDE;
#pragma unroll
            for (int kf = 0; kf < 4; kf++) {
                const uint32_t* p = qw + kf * 16 + 2 * t;
                uint2 x0 = *(const uint2*)(p);
                uint2 x2 = *(const uint2*)(p + 8);
                uint2 x1 = *(const uint2*)(p + 8 * AT_STRIDE);
                uint2 x3 = *(const uint2*)(p + 8 * AT_STRIDE + 8);
                qh[kf][0] = x0.x; ql[kf][0] = x0.y;
                qh[kf][1] = x1.x; ql[kf][1] = x1.y;
                qh[kf][2] = x2.x; ql[kf][2] = x2.y;
                qh[kf][3] = x3.x; ql[kf][3] = x3.y;
            }
        }
        if (kb + 64 < TT) {
            load_kv(cur ^ 1, kb + 64);
            asm volatile("cp.async.commit_group;\n" ::: "memory");
        }

        const uint32_t* sk = sm + AT_KT + cur * 64 * AT_STRIDE;
        const uint32_t* sv = sm + AT_VT + cur * 64 * AT_STRIDE;
        const float* bi = biasbuf + cur * 64;

        // ---- S = Q K^T (bf16x3) : 8 key n-tiles of 8 ----
        float s[8][4];
#pragma unroll
        for (int nt = 0; nt < 8; nt++) {
#pragma unroll
            for (int c = 0; c < 4; c++) s[nt][c] = 0.f;
#pragma unroll
            for (int kf = 0; kf < 4; kf++) {
                const uint32_t* p = sk + (nt * 8 + g) * AT_STRIDE + kf * 16 + 2 * t;
                uint2 y0 = *(const uint2*)(p);
                uint2 y1 = *(const uint2*)(p + 8);
                uint32_t bh[2] = {y0.x, y1.x};
                uint32_t bl[2] = {y0.y, y1.y};
                mma16816(s[nt], qh[kf], bh);
                mma16816(s[nt], qh[kf], bl);
                mma16816(s[nt], ql[kf], bh);
            }
        }

        // ---- scale + mask bias, row max ----
        float mn0 = -1e30f, mn1 = -1e30f;
#pragma unroll
        for (int nt = 0; nt < 8; nt++) {
            float b0 = bi[nt * 8 + 2 * t];
            float b1 = bi[nt * 8 + 2 * t + 1];
            s[nt][0] = fmaf(s[nt][0], SC, b0);
            s[nt][1] = fmaf(s[nt][1], SC, b1);
            s[nt][2] = fmaf(s[nt][2], SC, b0);
            s[nt][3] = fmaf(s[nt][3], SC, b1);
            mn0 = fmaxf(mn0, fmaxf(s[nt][0], s[nt][1]));
            mn1 = fmaxf(mn1, fmaxf(s[nt][2], s[nt][3]));
        }
        mn0 = fmaxf(mn0, __shfl_xor_sync(0xffffffffu, mn0, 1));
        mn0 = fmaxf(mn0, __shfl_xor_sync(0xffffffffu, mn0, 2));
        mn1 = fmaxf(mn1, __shfl_xor_sync(0xffffffffu, mn1, 1));
        mn1 = fmaxf(mn1, __shfl_xor_sync(0xffffffffu, mn1, 2));

        float M0 = fmaxf(m0, mn0);
        float M1 = fmaxf(m1, mn1);
        float f0 = ex2(m0 - M0);
        float f1 = ex2(m1 - M1);
        m0 = M0; m1 = M1;
        l0 *= f0; l1 *= f1;
#pragma unroll
        for (int dn = 0; dn < 8; dn++) {
            o[dn][0] *= f0; o[dn][1] *= f0;
            o[dn][2] *= f1; o[dn][3] *= f1;
        }

        // ---- P = exp2(s - m), partial row sums ----
#pragma unroll
        for (int nt = 0; nt < 8; nt++) {
            s[nt][0] = ex2(s[nt][0] - M0);
            s[nt][1] = ex2(s[nt][1] - M0);
            s[nt][2] = ex2(s[nt][2] - M1);
            s[nt][3] = ex2(s[nt][3] - M1);
            l0 += s[nt][0] + s[nt][1];
            l1 += s[nt][2] + s[nt][3];
        }

        // ---- O += P V (bf16x3, P repacked in registers) ----
#pragma unroll
        for (int kc = 0; kc < 4; kc++) {
            uint32_t pah[4], pal[4];
            pah[0] = pack_hi_lo(s[2 * kc][0],     s[2 * kc][1],     pal[0]);
            pah[1] = pack_hi_lo(s[2 * kc][2],     s[2 * kc][3],     pal[1]);
            pah[2] = pack_hi_lo(s[2 * kc + 1][0], s[2 * kc + 1][1], pal[2]);
            pah[3] = pack_hi_lo(s[2 * kc + 1][2], s[2 * kc + 1][3], pal[3]);
#pragma unroll
            for (int dn = 0; dn < 8; dn++) {
                const uint32_t* p = sv + (dn * 8 + g) * AT_STRIDE + kc * 16 + 2 * t;
                uint2 u0 = *(const uint2*)(p);
                uint2 u1 = *(const uint2*)(p + 8);
                uint32_t bh[2] = {u0.x, u1.x};
                uint32_t bl[2] = {u0.y, u1.y};
                mma16816(o[dn], pah, bh);
                mma16816(o[dn], pah, bl);
                mma16816(o[dn], pal, bh);
            }
        }

        cur ^= 1;
        __syncthreads();
    }

    // ---- finalize: row sums across quad, query mask, normalize, store ----
    l0 += __shfl_xor_sync(0xffffffffu, l0, 1);
    l0 += __shfl_xor_sync(0xffffffffu, l0, 2);
    l1 += __shfl_xor_sync(0xffffffffu, l1, 1);
    l1 += __shfl_xor_sync(0xffffffffu, l1, 2);

    const int qr0 = q0 + warp * 16 + g;
    const int qr1 = qr0 + 8;
    const float qm0 = (float)mask[b * TT + qr0];
    const float qm1 = (float)mask[b * TT + qr1];
    const float inv0 = (l0 > 0.f) ? qm0 / l0 : 0.f;
    const float inv1 = (l1 > 0.f) ? qm1 / l1 : 0.f;

    const int h = z & 15;
    float* c0 = g_ctx + (size_t)(b * TT + qr0) * EE + h * 64;
    float* c1 = g_ctx + (size_t)(b * TT + qr1) * EE + h * 64;
#pragma unroll
    for (int dn = 0; dn < 8; dn++) {
        const int col = dn * 8 + 2 * t;
        *(float2*)(c0 + col) = make_float2(o[dn][0] * inv0, o[dn][1] * inv0);
        *(float2*)(c1 + col) = make_float2(o[dn][2] * inv1, o[dn][3] * inv1);
    }
}

// ---------------------------------------------------------------------------
// out = LayerNorm(A + B) with ddof=1 std.
// ---------------------------------------------------------------------------
__global__ __launch_bounds__(256) void add_ln_kernel(
    const float* __restrict__ A, const float* __restrict__ Bv,
    const float* __restrict__ gam, const float* __restrict__ bet,
    float* __restrict__ out)
{
    __shared__ float shs[8], shq[8];
    const int row = blockIdx.x;
    const int tid = threadIdx.x;
    const size_t base = (size_t)row * EE + tid * 4;

    float4 a = *(const float4*)(A + base);
    float4 b = *(const float4*)(Bv + base);
    float x0 = a.x + b.x, x1 = a.y + b.y, x2 = a.z + b.z, x3 = a.w + b.w;

    float s = x0 + x1 + x2 + x3;
    float q = x0 * x0 + x1 * x1 + x2 * x2 + x3 * x3;
#pragma unroll
    for (int o = 16; o > 0; o >>= 1) {
        s += __shfl_xor_sync(0xffffffffu, s, o);
        q += __shfl_xor_sync(0xffffffffu, q, o);
    }
    if ((tid & 31) == 0) { shs[tid >> 5] = s; shq[tid >> 5] = q; }
    __syncthreads();
    float st = shs[0] + shs[1] + shs[2] + shs[3] + shs[4] + shs[5] + shs[6] + shs[7];
    float qt = shq[0] + shq[1] + shq[2] + shq[3] + shq[4] + shq[5] + shq[6] + shq[7];

    const float mean = st * (1.f / 1024.f);
    const float var = (qt - 1024.f * mean * mean) * (1.f / 1023.f);
    const float r = 1.f / (sqrtf(fmaxf(var, 0.f)) + 1e-5f);

    float4 g4 = *(const float4*)(gam + tid * 4);
    float4 b4 = *(const float4*)(bet + tid * 4);
    float4 o;
    o.x = (x0 - mean) * r * g4.x + b4.x;
    o.y = (x1 - mean) * r * g4.y + b4.y;
    o.z = (x2 - mean) * r * g4.z + b4.z;
    o.w = (x3 - mean) * r * g4.w + b4.w;
    *(float4*)(out + base) = o;
}

// ---------------------------------------------------------------------------
// Host launcher (graph-capturable: kernel launches only)
// ---------------------------------------------------------------------------
static inline void cvt(const float* src, uint32_t* dst, size_t n) {
    int n4 = (int)(n / 4);
    cvt_kernel<<<(n4 + 255) / 256, 256>>>((const float4*)src, (uint4*)dst, n4);
}

extern "C" void kernel_launch(void* const* d_in, const int* in_sizes, int n_in,
                              void* d_out, int out_size)
{
    const float* x    = (const float*)d_in[0];
    const int*   mask = (const int*)  d_in[1];
    const float* Wq   = (const float*)d_in[2];
    const float* Wk   = (const float*)d_in[3];
    const float* Wv   = (const float*)d_in[4];
    const float* Wo   = (const float*)d_in[5];
    const float* w1   = (const float*)d_in[6];
    const float* b1   = (const float*)d_in[7];
    const float* w2   = (const float*)d_in[8];
    const float* b2   = (const float*)d_in[9];
    const float* lng  = (const float*)d_in[10];
    const float* lnb  = (const float*)d_in[11];
    float* out = (float*)d_out;

    float *q, *k, *v, *ctx, *h, *tmp, *ff;
    cudaGetSymbolAddress((void**)&q,   g_q);
    cudaGetSymbolAddress((void**)&k,   g_k);
    cudaGetSymbolAddress((void**)&v,   g_v);
    cudaGetSymbolAddress((void**)&ctx, g_ctx);
    cudaGetSymbolAddress((void**)&h,   g_h);
    cudaGetSymbolAddress((void**)&tmp, g_tmp);
    cudaGetSymbolAddress((void**)&ff,  g_ff);

    uint32_t *x2, *ctx2, *h2, *ff2, *wq2, *wk2, *wv2, *wo2, *w12, *w22;
    uint32_t *q2, *k2, *vt2;
    cudaGetSymbolAddress((void**)&x2,   g_x2);
    cudaGetSymbolAddress((void**)&ctx2, g_ctx2);
    cudaGetSymbolAddress((void**)&h2,   g_h2);
    cudaGetSymbolAddress((void**)&ff2,  g_ff2);
    cudaGetSymbolAddress((void**)&wq2,  g_wq2);
    cudaGetSymbolAddress((void**)&wk2,  g_wk2);
    cudaGetSymbolAddress((void**)&wv2,  g_wv2);
    cudaGetSymbolAddress((void**)&wo2,  g_wo2);
    cudaGetSymbolAddress((void**)&w12,  g_w12);
    cudaGetSymbolAddress((void**)&w22,  g_w22);
    cudaGetSymbolAddress((void**)&q2,   g_q2);
    cudaGetSymbolAddress((void**)&k2,   g_k2);
    cudaGetSymbolAddress((void**)&vt2,  g_vt2);

    cudaFuncSetAttribute(gemm_bf16x3_kernel,
                         cudaFuncAttributeMaxDynamicSharedMemorySize, GEMM_SMEM);
    cudaFuncSetAttribute(attn_fused_kernel,
                         cudaFuncAttributeMaxDynamicSharedMemorySize, AT_SMEM);

    const dim3 thr(256);

    // Convert inputs + weights to interleaved bf16 hi/lo
    cvt(x,  x2,  (size_t)NTOK * EE);
    cvt(Wq, wq2, (size_t)EE * EE);
    cvt(Wk, wk2, (size_t)EE * EE);
    cvt(Wv, wv2, (size_t)EE * EE);
    cvt(Wo, wo2, (size_t)EE * EE);
    cvt(w1, w12, (size_t)FFDIM * EE);
    cvt(w2, w22, (size_t)EE * FFDIM);

    // QKV projections (tensor cores, bf16x3)
    gemm_bf16x3_kernel<<<dim3(64, 8), thr, GEMM_SMEM>>>(x2, wq2, nullptr, q, NTOK, EE, EE, 0);
    gemm_bf16x3_kernel<<<dim3(64, 8), thr, GEMM_SMEM>>>(x2, wk2, nullptr, k, NTOK, EE, EE, 0);
    gemm_bf16x3_kernel<<<dim3(64, 8), thr, GEMM_SMEM>>>(x2, wv2, nullptr, v, NTOK, EE, EE, 0);

    // Repack per-head operands for fused attention
    repack_qk_kernel<<<(NTOK * (EE / 2)) / 256, thr>>>(q, q2);
    repack_qk_kernel<<<(NTOK * (EE / 2)) / 256, thr>>>(k, k2);
    repack_vt_kernel<<<dim3(64, 2, 64), thr>>>(v);

    // Fused flash attention (tensor cores end-to-end)
    attn_fused_kernel<<<dim3(16, 64), thr, AT_SMEM>>>(mask);

    // Output projection + first residual LN
    cvt(ctx, ctx2, (size_t)NTOK * EE);
    gemm_bf16x3_kernel<<<dim3(64, 8), thr, GEMM_SMEM>>>(ctx2, wo2, nullptr, tmp, NTOK, EE, EE, 0);
    add_ln_kernel<<<NTOK, thr>>>(tmp, x, lng, lnb, h);

    // FFN + second residual LN
    cvt(h, h2, (size_t)NTOK * EE);
    gemm_bf16x3_kernel<<<dim3(64, 32), thr, GEMM_SMEM>>>(h2, w12, b1, ff, NTOK, FFDIM, EE, 3);
    cvt(ff, ff2, (size_t)NTOK * FFDIM);
    gemm_bf16x3_kernel<<<dim3(64, 8), thr, GEMM_SMEM>>>(ff2, w22, b2, tmp, NTOK, EE, FFDIM, 1);
    add_ln_kernel<<<NTOK, thr>>>(tmp, h, lng, lnb, out);
}